// round 14
// baseline (speedup 1.0000x reference)
#include <cuda_runtime.h>
#include <utility>

using ull = unsigned long long;

namespace tp {

constexpr int LMAX = 4;
constexpr int NM   = 25;    // (L+1)^2
constexpr int NB   = 128;
constexpr int NC   = 128;
constexpr int NCU  = NC / 2;     // 64 f32x2 (ull) elements per (b, m) row
constexpr int MAXNNZ = 8192;

constexpr int iabs(int v) { return v < 0 ? -v : v; }

struct Pat {
  int nnz;
  short seg[MAXNNZ];
  short m1[MAXNNZ];
  short m2[MAXNNZ];
};

// Replicates reference _build_cg_pattern() INCLUDING the sort.
constexpr Pat build_pat() {
  Pat p{};
  int n = 0;
  for (int lo = 0; lo <= LMAX; ++lo)
    for (int mo = -lo; mo <= lo; ++mo)
      for (int l1 = 0; l1 <= LMAX; ++l1)
        for (int u1 = -l1; u1 <= l1; ++u1)
          for (int l2 = 0; l2 <= LMAX; ++l2) {
            if (l2 < iabs(lo - l1) || l2 > lo + l1) continue;
            for (int u2 = -l2; u2 <= l2; ++u2) {
              if (iabs(u1 + u2) == iabs(mo) || iabs(u1 - u2) == iabs(mo)) {
                p.seg[n] = (short)(lo * (lo + 1) + mo);
                p.m1 [n] = (short)(l1 * (l1 + 1) + u1);
                p.m2 [n] = (short)(l2 * (l2 + 1) + u2);
                ++n;
              }
            }
          }
  p.nnz = n;
  return p;
}

constexpr Pat PAT = build_pat();
constexpr int NNZ = PAT.nnz;
static_assert(NNZ > 0 && NNZ < MAXNNZ, "nnz bounds");

constexpr int NG    = 8;   // segment groups; ONE group per CTA
constexpr int NT    = 256; // 8 warps = 4 b x 2 channel-halves
constexpr int CHUNK = 8;   // cg values per batch (4x LDS.128, duplicated)

// Flattened pair-major execution plan (counting-sort pair order per group;
// identical boundaries + order to R6/R11 -> rel_err must be 1.239262e-07).
struct Plan {
  int e[NG + 1];
  int mlo[NG], mhi[NG];
  unsigned u1[NG], u2[NG];
  int fb[NG + 1];
  short fseg[MAXNNZ];
  short fm1[MAXNNZ], fm2[MAXNNZ];
  short ffirst[MAXNNZ];
  short fcgi[MAXNNZ];
};

constexpr Plan build_plan() {
  Plan s{};
  int segstart[NM + 1] = {};
  {
    int pos = 0;
    for (int m = 0; m <= NM; ++m) {
      while (pos < NNZ && PAT.seg[pos] < m) ++pos;
      segstart[m] = pos;
    }
  }
  s.e[0] = 0; s.e[NG] = NNZ;
  for (int g = 1; g < NG; ++g) {
    int target = (NNZ * g) / NG;
    int best = 0, bd = 1 << 30;
    for (int m = 0; m <= NM; ++m) {
      int d = segstart[m] - target; if (d < 0) d = -d;
      if (d < bd) { bd = d; best = segstart[m]; }
    }
    s.e[g] = best;
  }
  int nf = 0;
  for (int g = 0; g < NG; ++g) {
    const int e0 = s.e[g], e1 = s.e[g + 1];
    s.mlo[g] = (e0 < NNZ) ? (int)PAT.seg[e0] : NM;
    s.mhi[g] = (e1 < NNZ) ? (int)PAT.seg[e1] : NM;
    s.fb[g] = nf;
    unsigned u1 = 0, u2 = 0;
    int cnt[NM * NM] = {};
    for (int j = e0; j < e1; ++j) {
      u1 |= 1u << PAT.m1[j];
      u2 |= 1u << PAT.m2[j];
      cnt[PAT.m1[j] * NM + PAT.m2[j]]++;
    }
    int off[NM * NM] = {};
    int base[NM * NM] = {};
    for (int pid = 0; pid < NM * NM; ++pid) {
      if (cnt[pid]) { off[pid] = nf; base[pid] = nf; nf += cnt[pid]; }
    }
    for (int j = e0; j < e1; ++j) {
      int pid = PAT.m1[j] * NM + PAT.m2[j];
      int pos = off[pid]++;
      s.fseg[pos]  = PAT.seg[j];
      s.fm1[pos]   = PAT.m1[j];
      s.fm2[pos]   = PAT.m2[j];
      s.fcgi[pos]  = (short)j;
      s.ffirst[pos] = (short)(pos == base[pid]);
    }
    s.u1[g] = u1; s.u2[g] = u2;
  }
  s.fb[NG] = nf;
  return s;
}

constexpr Plan PLAN = build_plan();

// Packed cg layout: plan order, group bases padded to CHUNK so every batch is
// 16B-aligned LDS.128-able, tail over-read safe. Duplicated (8B/entry).
struct Pack {
  int delta[NG];
  short idx[MAXNNZ + CHUNK * NG];
  int total;
};

constexpr Pack build_pack() {
  Pack k{};
  int p = 0;
  for (int g = 0; g < NG; ++g) {
    k.delta[g] = p - PLAN.fb[g];
    const int len = PLAN.fb[g + 1] - PLAN.fb[g];
    for (int i = 0; i < len; ++i) k.idx[p + i] = PLAN.fcgi[PLAN.fb[g] + i];
    p += (len + CHUNK - 1) / CHUNK * CHUNK;
  }
  k.total = p;
  return k;
}

constexpr Pack PK = build_pack();
constexpr int NF2 = PK.total;

struct IdxArr { short v[MAXNNZ + CHUNK * NG]; };
constexpr IdxArr make_idx() {
  IdxArr a{};
  for (int i = 0; i < MAXNNZ + CHUNK * NG; ++i) a.v[i] = PK.idx[i];
  return a;
}
__device__ const IdxArr d_pidx = make_idx();

// ---- packed f32x2 math (sm_103a) ----
__device__ __forceinline__ ull mul2(ull a, ull b) {
  ull r;
  asm("mul.rn.f32x2 %0, %1, %2;" : "=l"(r) : "l"(a), "l"(b));
  return r;
}
__device__ __forceinline__ void fma2(ull& d, ull a, ull b) {
  asm("fma.rn.f32x2 %0, %1, %2, %3;" : "=l"(d) : "l"(a), "l"(b), "l"(d));
}

// All PLAN/PK reads appear ONLY in template-argument position.

template<int FIRST, int A, int B2, int SEGR>
__device__ __forceinline__ void step(ull* __restrict__ acc,
                                     const ull* __restrict__ x1r,
                                     const ull* __restrict__ x2r,
                                     ull& p, ull cgv) {
  if constexpr (FIRST) p = mul2(x1r[A], x2r[B2]);
  fma2(acc[SEGR], cgv, p);
}

template<int PPOS, int N>
__device__ __forceinline__ void load_cg(ull* __restrict__ buf,
                                        const ull* __restrict__ scg) {
  const ulonglong2* v = reinterpret_cast<const ulonglong2*>(scg + PPOS);
#pragma unroll
  for (int i = 0; i < (N + 1) / 2; ++i) {
    ulonglong2 t = v[i];
    buf[2 * i] = t.x; buf[2 * i + 1] = t.y;
  }
}

template<int MLO, int POS, int DELTA, int... K>
__device__ __forceinline__ void run_chunk(ull* __restrict__ acc,
                                          const ull* __restrict__ x1r,
                                          const ull* __restrict__ x2r,
                                          const ull* __restrict__ scg, ull& p,
                                          std::integer_sequence<int, K...>) {
  ull cgv[CHUNK];
  load_cg<POS + DELTA, sizeof...(K)>(cgv, scg);
  ( step<PLAN.ffirst[POS + K], PLAN.fm1[POS + K], PLAN.fm2[POS + K],
         PLAN.fseg[POS + K] - MLO>(acc, x1r, x2r, p, cgv[K]), ... );
}

template<int MLO, int FB, int FE, int DELTA, int... C>
__device__ __forceinline__ void run_chunks(ull* __restrict__ acc,
                                           const ull* __restrict__ x1r,
                                           const ull* __restrict__ x2r,
                                           const ull* __restrict__ scg,
                                           std::integer_sequence<int, C...>) {
  ull p = 0;
  ( run_chunk<MLO, FB + C * CHUNK, DELTA>(
        acc, x1r, x2r, scg, p,
        std::make_integer_sequence<int,
            ((FE - (FB + C * CHUNK)) < CHUNK ? (FE - (FB + C * CHUNK)) : CHUNK)>{}),
    ... );
}

template<unsigned MASK, int M>
__device__ __forceinline__ void load1(ull* __restrict__ r,
                                      const ull* __restrict__ src, int c) {
  if constexpr ((MASK >> M) & 1u) r[M] = src[M * NCU + c];
}
template<unsigned MASK, int... M>
__device__ __forceinline__ void loadm(ull* __restrict__ r,
                                      const ull* __restrict__ src, int c,
                                      std::integer_sequence<int, M...>) {
  ( load1<MASK, M>(r, src, c), ... );
}

template<int MLO, int... S>
__device__ __forceinline__ void storem(ull* __restrict__ outu,
                                       const ull* __restrict__ acc, int c,
                                       std::integer_sequence<int, S...>) {
  ( (outu[(MLO + S) * NCU + c] = acc[S]), ... );
}

template<int MLO, int MHI, int FB, int FE, int DELTA, unsigned U1, unsigned U2>
__device__ __forceinline__ void rg(const ull* __restrict__ x1u,
                                   const ull* __restrict__ x2u,
                                   ull* __restrict__ outu,
                                   const ull* __restrict__ scg, int c) {
  ull x1r[NM], x2r[NM];
  loadm<U1>(x1r, x1u, c, std::make_integer_sequence<int, NM>{});
  loadm<U2>(x2r, x2u, c, std::make_integer_sequence<int, NM>{});
  ull acc[MHI - MLO] = {};
  run_chunks<MLO, FB, FE, DELTA>(
      acc, x1r, x2r, scg,
      std::make_integer_sequence<int, (FE - FB + CHUNK - 1) / CHUNK>{});
  storem<MLO>(outu, acc, c, std::make_integer_sequence<int, MHI - MLO>{});
}

template<int G>
__device__ __forceinline__ void rung(const ull* __restrict__ x1u,
                                     const ull* __restrict__ x2u,
                                     ull* __restrict__ outu,
                                     const ull* __restrict__ scg, int c) {
  rg<PLAN.mlo[G], PLAN.mhi[G], PLAN.fb[G], PLAN.fb[G + 1], PK.delta[G],
     PLAN.u1[G], PLAN.u2[G]>(x1u, x2u, outu, scg, c);
}

// CTA = (group, b-quad): 8 warps = 4 b x 2 channel-halves, all running the
// SAME group region. Grid = 8 groups x 32 quads = 256 CTAs (>= 148: clears
// the documented sm-issue-throttle for >32KB bodies at low grid), 2 CTAs/SM
// -> 16 warps/SM resident.
__global__ void __launch_bounds__(NT, 2)
tp_kernel(const float* __restrict__ x1, const float* __restrict__ x2,
          const float* __restrict__ cg, float* __restrict__ out) {
  __shared__ __align__(16) ull scg[NF2];   // packed cg, f32x2-duplicated
  const int tid = threadIdx.x;
  for (int i = tid; i < NF2; i += NT) {
    ull u = (ull)__float_as_uint(__ldg(cg + d_pidx.v[i]));
    scg[i] = u | (u << 32);
  }
  __syncthreads();

  const int g    = blockIdx.x >> 5;        // group: uniform per CTA
  const int quad = blockIdx.x & 31;        // b-quad
  const int wid  = tid >> 5;
  const int b    = quad * 4 + (wid >> 1);  // 4 b per CTA
  const int h    = wid & 1;                // channel half
  const int c    = h * 32 + (tid & 31);    // f32x2 lane index within row

  const ull* x1u = reinterpret_cast<const ull*>(x1) + b * (NM * NCU);
  const ull* x2u = reinterpret_cast<const ull*>(x2) + b * (NM * NCU);
  ull*       ou  = reinterpret_cast<ull*>(out)      + b * (NM * NCU);

  switch (g) {
    case 0: rung<0>(x1u, x2u, ou, scg, c); break;
    case 1: rung<1>(x1u, x2u, ou, scg, c); break;
    case 2: rung<2>(x1u, x2u, ou, scg, c); break;
    case 3: rung<3>(x1u, x2u, ou, scg, c); break;
    case 4: rung<4>(x1u, x2u, ou, scg, c); break;
    case 5: rung<5>(x1u, x2u, ou, scg, c); break;
    case 6: rung<6>(x1u, x2u, ou, scg, c); break;
    case 7: rung<7>(x1u, x2u, ou, scg, c); break;
  }
}

// ---- generic fallback (only if runtime nnz != compile-time NNZ) ----
__global__ void tp_generic(const float* __restrict__ x1, const float* __restrict__ x2,
                           const float* __restrict__ cg,
                           const int* __restrict__ M1, const int* __restrict__ M2,
                           const int* __restrict__ seg, int nnz,
                           float* __restrict__ out) {
  const int b = blockIdx.x;
  const int c = threadIdx.x;
  const float* x1b = x1 + b * NM * NC;
  const float* x2b = x2 + b * NM * NC;
  float acc = 0.f;
  int cur = seg[0];
  for (int i = 0; i < nnz; ++i) {
    int s = seg[i];
    if (s != cur) { out[(b * NM + cur) * NC + c] = acc; acc = 0.f; cur = s; }
    acc += cg[i] * x1b[M1[i] * NC + c] * x2b[M2[i] * NC + c];
  }
  out[(b * NM + cur) * NC + c] = acc;
}

}  // namespace tp

extern "C" void kernel_launch(void* const* d_in, const int* in_sizes, int n_in,
                              void* d_out, int out_size) {
  const float* x1 = (const float*)d_in[0];
  const float* x2 = (const float*)d_in[1];
  const float* cg = (const float*)d_in[2];
  const int*   M1 = (const int*)  d_in[3];
  const int*   M2 = (const int*)  d_in[4];
  const int*   sg = (const int*)  d_in[5];
  float* out = (float*)d_out;

  if (in_sizes[2] == tp::NNZ) {
    tp::tp_kernel<<<tp::NG * 32, tp::NT>>>(x1, x2, cg, out);
  } else {
    cudaMemsetAsync(d_out, 0, (size_t)out_size * sizeof(float));
    tp::tp_generic<<<tp::NB, tp::NC>>>(x1, x2, cg, M1, M2, sg, in_sizes[2], out);
  }
}

// round 15
// speedup vs baseline: 1.1530x; 1.1530x over previous
#include <cuda_runtime.h>
#include <utility>

using ull = unsigned long long;

namespace tp {

constexpr int LMAX = 4;
constexpr int NM   = 25;    // (L+1)^2
constexpr int NB   = 128;
constexpr int NC   = 128;
constexpr int NCU  = NC / 2;     // 64 f32x2 (ull) elements per (b, m) row
constexpr int MAXNNZ = 8192;

constexpr int iabs(int v) { return v < 0 ? -v : v; }

struct Pat {
  int nnz;
  short seg[MAXNNZ];
  short m1[MAXNNZ];
  short m2[MAXNNZ];
};

// Replicates reference _build_cg_pattern() INCLUDING the sort.
constexpr Pat build_pat() {
  Pat p{};
  int n = 0;
  for (int lo = 0; lo <= LMAX; ++lo)
    for (int mo = -lo; mo <= lo; ++mo)
      for (int l1 = 0; l1 <= LMAX; ++l1)
        for (int u1 = -l1; u1 <= l1; ++u1)
          for (int l2 = 0; l2 <= LMAX; ++l2) {
            if (l2 < iabs(lo - l1) || l2 > lo + l1) continue;
            for (int u2 = -l2; u2 <= l2; ++u2) {
              if (iabs(u1 + u2) == iabs(mo) || iabs(u1 - u2) == iabs(mo)) {
                p.seg[n] = (short)(lo * (lo + 1) + mo);
                p.m1 [n] = (short)(l1 * (l1 + 1) + u1);
                p.m2 [n] = (short)(l2 * (l2 + 1) + u2);
                ++n;
              }
            }
          }
  p.nnz = n;
  return p;
}

constexpr Pat PAT = build_pat();
constexpr int NNZ = PAT.nnz;
static_assert(NNZ > 0 && NNZ < MAXNNZ, "nnz bounds");

constexpr int NG    = 8;   // segment groups; ONE group per CTA (shared I-stream)
constexpr int NT    = 512; // 16 warps = 8 b x 2 channel-halves
constexpr int CHUNK = 8;   // cg values per pipeline stage (4x LDS.128)

// Flattened pair-major execution plan (counting-sort pair order per group;
// identical boundaries + order to R6/R11 -> rel_err must be 1.239262e-07).
struct Plan {
  int e[NG + 1];
  int mlo[NG], mhi[NG];
  unsigned u1[NG], u2[NG];
  int fb[NG + 1];
  short fseg[MAXNNZ];
  short fm1[MAXNNZ], fm2[MAXNNZ];
  short ffirst[MAXNNZ];
  short fcgi[MAXNNZ];
};

constexpr Plan build_plan() {
  Plan s{};
  int segstart[NM + 1] = {};
  {
    int pos = 0;
    for (int m = 0; m <= NM; ++m) {
      while (pos < NNZ && PAT.seg[pos] < m) ++pos;
      segstart[m] = pos;
    }
  }
  s.e[0] = 0; s.e[NG] = NNZ;
  for (int g = 1; g < NG; ++g) {
    int target = (NNZ * g) / NG;
    int best = 0, bd = 1 << 30;
    for (int m = 0; m <= NM; ++m) {
      int d = segstart[m] - target; if (d < 0) d = -d;
      if (d < bd) { bd = d; best = segstart[m]; }
    }
    s.e[g] = best;
  }
  int nf = 0;
  for (int g = 0; g < NG; ++g) {
    const int e0 = s.e[g], e1 = s.e[g + 1];
    s.mlo[g] = (e0 < NNZ) ? (int)PAT.seg[e0] : NM;
    s.mhi[g] = (e1 < NNZ) ? (int)PAT.seg[e1] : NM;
    s.fb[g] = nf;
    unsigned u1 = 0, u2 = 0;
    int cnt[NM * NM] = {};
    for (int j = e0; j < e1; ++j) {
      u1 |= 1u << PAT.m1[j];
      u2 |= 1u << PAT.m2[j];
      cnt[PAT.m1[j] * NM + PAT.m2[j]]++;
    }
    int off[NM * NM] = {};
    int base[NM * NM] = {};
    for (int pid = 0; pid < NM * NM; ++pid) {
      if (cnt[pid]) { off[pid] = nf; base[pid] = nf; nf += cnt[pid]; }
    }
    for (int j = e0; j < e1; ++j) {
      int pid = PAT.m1[j] * NM + PAT.m2[j];
      int pos = off[pid]++;
      s.fseg[pos]  = PAT.seg[j];
      s.fm1[pos]   = PAT.m1[j];
      s.fm2[pos]   = PAT.m2[j];
      s.fcgi[pos]  = (short)j;
      s.ffirst[pos] = (short)(pos == base[pid]);
    }
    s.u1[g] = u1; s.u2[g] = u2;
  }
  s.fb[NG] = nf;
  return s;
}

constexpr Plan PLAN = build_plan();

// Packed cg layout: plan order, group bases padded to CHUNK so every stage is
// 16B-aligned LDS.128-able, tail over-read safe. Duplicated (8B/entry).
struct Pack {
  int delta[NG];
  short idx[MAXNNZ + CHUNK * NG];
  int total;
};

constexpr Pack build_pack() {
  Pack k{};
  int p = 0;
  for (int g = 0; g < NG; ++g) {
    k.delta[g] = p - PLAN.fb[g];
    const int len = PLAN.fb[g + 1] - PLAN.fb[g];
    for (int i = 0; i < len; ++i) k.idx[p + i] = PLAN.fcgi[PLAN.fb[g] + i];
    p += (len + CHUNK - 1) / CHUNK * CHUNK;
  }
  k.total = p;
  return k;
}

constexpr Pack PK = build_pack();
constexpr int NF2 = PK.total;

struct IdxArr { short v[MAXNNZ + CHUNK * NG]; };
constexpr IdxArr make_idx() {
  IdxArr a{};
  for (int i = 0; i < MAXNNZ + CHUNK * NG; ++i) a.v[i] = PK.idx[i];
  return a;
}
__device__ const IdxArr d_pidx = make_idx();

// ---- packed f32x2 math (sm_103a) ----
__device__ __forceinline__ ull mul2(ull a, ull b) {
  ull r;
  asm("mul.rn.f32x2 %0, %1, %2;" : "=l"(r) : "l"(a), "l"(b));
  return r;
}
__device__ __forceinline__ void fma2(ull& d, ull a, ull b) {
  asm("fma.rn.f32x2 %0, %1, %2, %3;" : "=l"(d) : "l"(a), "l"(b), "l"(d));
}

// All PLAN/PK reads appear ONLY in template-argument position.

template<int FIRST, int A, int B2, int SEGR>
__device__ __forceinline__ void step(ull* __restrict__ acc,
                                     const ull* __restrict__ x1r,
                                     const ull* __restrict__ x2r,
                                     ull& p, ull cgv) {
  if constexpr (FIRST) p = mul2(x1r[A], x2r[B2]);
  fma2(acc[SEGR], cgv, p);
}

// Load one full CHUNK of duplicated cg values (4x LDS.128). PPOS is
// CHUNK-aligned (group bases padded); padding slots initialized, so the
// tail over-read is always safe.
template<int PPOS>
__device__ __forceinline__ void load_chunk(ull* __restrict__ buf,
                                           const ull* __restrict__ scg) {
  const ulonglong2* v = reinterpret_cast<const ulonglong2*>(scg + PPOS);
#pragma unroll
  for (int i = 0; i < CHUNK / 2; ++i) {
    ulonglong2 t = v[i];
    buf[2 * i] = t.x; buf[2 * i + 1] = t.y;
  }
}

template<int MLO, int POS, int... K>
__device__ __forceinline__ void compute_chunk(ull* __restrict__ acc,
                                              const ull* __restrict__ x1r,
                                              const ull* __restrict__ x2r,
                                              ull& p, const ull* __restrict__ buf,
                                              std::integer_sequence<int, K...>) {
  ( step<PLAN.ffirst[POS + K], PLAN.fm1[POS + K], PLAN.fm2[POS + K],
         PLAN.fseg[POS + K] - MLO>(acc, x1r, x2r, p, buf[K]), ... );
}

// Double-buffered pipeline: while chunk at POS computes from one buffer, the
// next chunk's 4 LDS.128 (data-independent) fill the other buffer, so the
// ~30-cycle shared-memory latency overlaps the FMA stream.
template<int MLO, int FE, int DELTA, int POS, int BUF>
__device__ __forceinline__ void pipe(ull* __restrict__ acc,
                                     const ull* __restrict__ x1r,
                                     const ull* __restrict__ x2r,
                                     const ull* __restrict__ scg, ull& p,
                                     ull (&b0)[CHUNK], ull (&b1)[CHUNK]) {
  constexpr int N = (FE - POS < CHUNK) ? (FE - POS) : CHUNK;
  if constexpr (POS + N < FE)
    load_chunk<POS + N + DELTA>(BUF ? b0 : b1, scg);
  compute_chunk<MLO, POS>(acc, x1r, x2r, p, BUF ? b1 : b0,
                          std::make_integer_sequence<int, N>{});
  if constexpr (POS + N < FE)
    pipe<MLO, FE, DELTA, POS + N, BUF ^ 1>(acc, x1r, x2r, scg, p, b0, b1);
}

template<unsigned MASK, int M>
__device__ __forceinline__ void load1(ull* __restrict__ r,
                                      const ull* __restrict__ src, int c) {
  if constexpr ((MASK >> M) & 1u) r[M] = src[M * NCU + c];
}
template<unsigned MASK, int... M>
__device__ __forceinline__ void loadm(ull* __restrict__ r,
                                      const ull* __restrict__ src, int c,
                                      std::integer_sequence<int, M...>) {
  ( load1<MASK, M>(r, src, c), ... );
}

template<int MLO, int... S>
__device__ __forceinline__ void storem(ull* __restrict__ outu,
                                       const ull* __restrict__ acc, int c,
                                       std::integer_sequence<int, S...>) {
  ( (outu[(MLO + S) * NCU + c] = acc[S]), ... );
}

template<int MLO, int MHI, int FB, int FE, int DELTA, unsigned U1, unsigned U2>
__device__ __forceinline__ void rg(const ull* __restrict__ x1u,
                                   const ull* __restrict__ x2u,
                                   ull* __restrict__ outu,
                                   const ull* __restrict__ scg, int c) {
  ull x1r[NM], x2r[NM];
  loadm<U1>(x1r, x1u, c, std::make_integer_sequence<int, NM>{});
  loadm<U2>(x2r, x2u, c, std::make_integer_sequence<int, NM>{});
  ull acc[MHI - MLO] = {};
  ull b0[CHUNK], b1[CHUNK];
  load_chunk<FB + DELTA>(b0, scg);
  ull p = 0;
  pipe<MLO, FE, DELTA, FB, 0>(acc, x1r, x2r, scg, p, b0, b1);
  storem<MLO>(outu, acc, c, std::make_integer_sequence<int, MHI - MLO>{});
}

template<int G>
__device__ __forceinline__ void rung(const ull* __restrict__ x1u,
                                     const ull* __restrict__ x2u,
                                     ull* __restrict__ outu,
                                     const ull* __restrict__ scg, int c) {
  rg<PLAN.mlo[G], PLAN.mhi[G], PLAN.fb[G], PLAN.fb[G + 1], PK.delta[G],
     PLAN.u1[G], PLAN.u2[G]>(x1u, x2u, outu, scg, c);
}

// CTA = (group, b-octet): all 16 warps execute the SAME ~25KB group region
// (one I-stream per SM) on 8 b's x 2 channel-halves. Grid = 8 x 16 = 128
// CTAs -> one uniform wave, 1 CTA/SM. (R11-best layout.)
__global__ void __launch_bounds__(NT, 1)
tp_kernel(const float* __restrict__ x1, const float* __restrict__ x2,
          const float* __restrict__ cg, float* __restrict__ out) {
  __shared__ __align__(16) ull scg[NF2];   // packed cg, f32x2-duplicated
  const int tid = threadIdx.x;
  for (int i = tid; i < NF2; i += NT) {
    ull u = (ull)__float_as_uint(__ldg(cg + d_pidx.v[i]));
    scg[i] = u | (u << 32);
  }
  __syncthreads();

  const int g   = blockIdx.x >> 4;         // group: uniform per CTA
  const int oct = blockIdx.x & 15;         // b-octet
  const int wid = tid >> 5;
  const int b   = oct * 8 + (wid >> 1);    // 8 b per CTA
  const int h   = wid & 1;                 // channel half
  const int c   = h * 32 + (tid & 31);     // f32x2 lane index within row

  const ull* x1u = reinterpret_cast<const ull*>(x1) + b * (NM * NCU);
  const ull* x2u = reinterpret_cast<const ull*>(x2) + b * (NM * NCU);
  ull*       ou  = reinterpret_cast<ull*>(out)      + b * (NM * NCU);

  switch (g) {
    case 0: rung<0>(x1u, x2u, ou, scg, c); break;
    case 1: rung<1>(x1u, x2u, ou, scg, c); break;
    case 2: rung<2>(x1u, x2u, ou, scg, c); break;
    case 3: rung<3>(x1u, x2u, ou, scg, c); break;
    case 4: rung<4>(x1u, x2u, ou, scg, c); break;
    case 5: rung<5>(x1u, x2u, ou, scg, c); break;
    case 6: rung<6>(x1u, x2u, ou, scg, c); break;
    case 7: rung<7>(x1u, x2u, ou, scg, c); break;
  }
}

// ---- generic fallback (only if runtime nnz != compile-time NNZ) ----
__global__ void tp_generic(const float* __restrict__ x1, const float* __restrict__ x2,
                           const float* __restrict__ cg,
                           const int* __restrict__ M1, const int* __restrict__ M2,
                           const int* __restrict__ seg, int nnz,
                           float* __restrict__ out) {
  const int b = blockIdx.x;
  const int c = threadIdx.x;
  const float* x1b = x1 + b * NM * NC;
  const float* x2b = x2 + b * NM * NC;
  float acc = 0.f;
  int cur = seg[0];
  for (int i = 0; i < nnz; ++i) {
    int s = seg[i];
    if (s != cur) { out[(b * NM + cur) * NC + c] = acc; acc = 0.f; cur = s; }
    acc += cg[i] * x1b[M1[i] * NC + c] * x2b[M2[i] * NC + c];
  }
  out[(b * NM + cur) * NC + c] = acc;
}

}  // namespace tp

extern "C" void kernel_launch(void* const* d_in, const int* in_sizes, int n_in,
                              void* d_out, int out_size) {
  const float* x1 = (const float*)d_in[0];
  const float* x2 = (const float*)d_in[1];
  const float* cg = (const float*)d_in[2];
  const int*   M1 = (const int*)  d_in[3];
  const int*   M2 = (const int*)  d_in[4];
  const int*   sg = (const int*)  d_in[5];
  float* out = (float*)d_out;

  if (in_sizes[2] == tp::NNZ) {
    tp::tp_kernel<<<tp::NG * 16, tp::NT>>>(x1, x2, cg, out);
  } else {
    cudaMemsetAsync(d_out, 0, (size_t)out_size * sizeof(float));
    tp::tp_generic<<<tp::NB, tp::NC>>>(x1, x2, cg, M1, M2, sg, in_sizes[2], out);
  }
}

// round 16
// speedup vs baseline: 1.1555x; 1.0022x over previous
#include <cuda_runtime.h>
#include <utility>

using ull = unsigned long long;

namespace tp {

constexpr int LMAX = 4;
constexpr int NM   = 25;    // (L+1)^2
constexpr int NB   = 128;
constexpr int NC   = 128;
constexpr int NCU  = NC / 2;     // 64 f32x2 (ull) elements per (b, m) row
constexpr int MAXNNZ = 8192;

constexpr int iabs(int v) { return v < 0 ? -v : v; }

struct Pat {
  int nnz;
  short seg[MAXNNZ];
  short m1[MAXNNZ];
  short m2[MAXNNZ];
};

// Replicates reference _build_cg_pattern() INCLUDING the sort.
constexpr Pat build_pat() {
  Pat p{};
  int n = 0;
  for (int lo = 0; lo <= LMAX; ++lo)
    for (int mo = -lo; mo <= lo; ++mo)
      for (int l1 = 0; l1 <= LMAX; ++l1)
        for (int u1 = -l1; u1 <= l1; ++u1)
          for (int l2 = 0; l2 <= LMAX; ++l2) {
            if (l2 < iabs(lo - l1) || l2 > lo + l1) continue;
            for (int u2 = -l2; u2 <= l2; ++u2) {
              if (iabs(u1 + u2) == iabs(mo) || iabs(u1 - u2) == iabs(mo)) {
                p.seg[n] = (short)(lo * (lo + 1) + mo);
                p.m1 [n] = (short)(l1 * (l1 + 1) + u1);
                p.m2 [n] = (short)(l2 * (l2 + 1) + u2);
                ++n;
              }
            }
          }
  p.nnz = n;
  return p;
}

constexpr Pat PAT = build_pat();
constexpr int NNZ = PAT.nnz;
static_assert(NNZ > 0 && NNZ < MAXNNZ, "nnz bounds");

constexpr int NG    = 8;   // segment groups; ONE group per CTA (shared I-stream)
constexpr int NT    = 512; // 16 warps = 8 b x 2 channel-halves
constexpr int CHUNK = 8;   // cg values per batch (4x LDS.128)
constexpr int SYNCEVERY = 12;  // chunks between re-convergence barriers (~4KB SASS)

// Flattened pair-major execution plan (counting-sort pair order per group;
// identical boundaries + order to R6/R11 -> rel_err must be 1.239262e-07).
struct Plan {
  int e[NG + 1];
  int mlo[NG], mhi[NG];
  unsigned u1[NG], u2[NG];
  int fb[NG + 1];
  short fseg[MAXNNZ];
  short fm1[MAXNNZ], fm2[MAXNNZ];
  short ffirst[MAXNNZ];
  short fcgi[MAXNNZ];
};

constexpr Plan build_plan() {
  Plan s{};
  int segstart[NM + 1] = {};
  {
    int pos = 0;
    for (int m = 0; m <= NM; ++m) {
      while (pos < NNZ && PAT.seg[pos] < m) ++pos;
      segstart[m] = pos;
    }
  }
  s.e[0] = 0; s.e[NG] = NNZ;
  for (int g = 1; g < NG; ++g) {
    int target = (NNZ * g) / NG;
    int best = 0, bd = 1 << 30;
    for (int m = 0; m <= NM; ++m) {
      int d = segstart[m] - target; if (d < 0) d = -d;
      if (d < bd) { bd = d; best = segstart[m]; }
    }
    s.e[g] = best;
  }
  int nf = 0;
  for (int g = 0; g < NG; ++g) {
    const int e0 = s.e[g], e1 = s.e[g + 1];
    s.mlo[g] = (e0 < NNZ) ? (int)PAT.seg[e0] : NM;
    s.mhi[g] = (e1 < NNZ) ? (int)PAT.seg[e1] : NM;
    s.fb[g] = nf;
    unsigned u1 = 0, u2 = 0;
    int cnt[NM * NM] = {};
    for (int j = e0; j < e1; ++j) {
      u1 |= 1u << PAT.m1[j];
      u2 |= 1u << PAT.m2[j];
      cnt[PAT.m1[j] * NM + PAT.m2[j]]++;
    }
    int off[NM * NM] = {};
    int base[NM * NM] = {};
    for (int pid = 0; pid < NM * NM; ++pid) {
      if (cnt[pid]) { off[pid] = nf; base[pid] = nf; nf += cnt[pid]; }
    }
    for (int j = e0; j < e1; ++j) {
      int pid = PAT.m1[j] * NM + PAT.m2[j];
      int pos = off[pid]++;
      s.fseg[pos]  = PAT.seg[j];
      s.fm1[pos]   = PAT.m1[j];
      s.fm2[pos]   = PAT.m2[j];
      s.fcgi[pos]  = (short)j;
      s.ffirst[pos] = (short)(pos == base[pid]);
    }
    s.u1[g] = u1; s.u2[g] = u2;
  }
  s.fb[NG] = nf;
  return s;
}

constexpr Plan PLAN = build_plan();

// Packed cg layout: plan order, group bases padded to CHUNK so every batch is
// 16B-aligned LDS.128-able, tail over-read safe. Duplicated (8B/entry).
struct Pack {
  int delta[NG];
  short idx[MAXNNZ + CHUNK * NG];
  int total;
};

constexpr Pack build_pack() {
  Pack k{};
  int p = 0;
  for (int g = 0; g < NG; ++g) {
    k.delta[g] = p - PLAN.fb[g];
    const int len = PLAN.fb[g + 1] - PLAN.fb[g];
    for (int i = 0; i < len; ++i) k.idx[p + i] = PLAN.fcgi[PLAN.fb[g] + i];
    p += (len + CHUNK - 1) / CHUNK * CHUNK;
  }
  k.total = p;
  return k;
}

constexpr Pack PK = build_pack();
constexpr int NF2 = PK.total;

struct IdxArr { short v[MAXNNZ + CHUNK * NG]; };
constexpr IdxArr make_idx() {
  IdxArr a{};
  for (int i = 0; i < MAXNNZ + CHUNK * NG; ++i) a.v[i] = PK.idx[i];
  return a;
}
__device__ const IdxArr d_pidx = make_idx();

// ---- packed f32x2 math (sm_103a) ----
__device__ __forceinline__ ull mul2(ull a, ull b) {
  ull r;
  asm("mul.rn.f32x2 %0, %1, %2;" : "=l"(r) : "l"(a), "l"(b));
  return r;
}
__device__ __forceinline__ void fma2(ull& d, ull a, ull b) {
  asm("fma.rn.f32x2 %0, %1, %2, %3;" : "=l"(d) : "l"(a), "l"(b), "l"(d));
}

// All PLAN/PK reads appear ONLY in template-argument position.

template<int FIRST, int A, int B2, int SEGR>
__device__ __forceinline__ void step(ull* __restrict__ acc,
                                     const ull* __restrict__ x1r,
                                     const ull* __restrict__ x2r,
                                     ull& p, ull cgv) {
  if constexpr (FIRST) p = mul2(x1r[A], x2r[B2]);
  fma2(acc[SEGR], cgv, p);
}

template<int PPOS, int N>
__device__ __forceinline__ void load_cg(ull* __restrict__ buf,
                                        const ull* __restrict__ scg) {
  const ulonglong2* v = reinterpret_cast<const ulonglong2*>(scg + PPOS);
#pragma unroll
  for (int i = 0; i < (N + 1) / 2; ++i) {
    ulonglong2 t = v[i];
    buf[2 * i] = t.x; buf[2 * i + 1] = t.y;
  }
}

// One chunk of <=CHUNK entries, followed (every SYNCEVERY-th chunk) by a CTA
// barrier that re-converges all 16 warps so the shared ~4KB code window stays
// resident in the per-SMSP L0 I$. All warps of a CTA run the SAME group ->
// identical barrier counts -> safe.
template<int MLO, int POS, int DELTA, int CIDX, int... K>
__device__ __forceinline__ void run_chunk(ull* __restrict__ acc,
                                          const ull* __restrict__ x1r,
                                          const ull* __restrict__ x2r,
                                          const ull* __restrict__ scg, ull& p,
                                          std::integer_sequence<int, K...>) {
  ull cgv[CHUNK];
  load_cg<POS + DELTA, sizeof...(K)>(cgv, scg);
  ( step<PLAN.ffirst[POS + K], PLAN.fm1[POS + K], PLAN.fm2[POS + K],
         PLAN.fseg[POS + K] - MLO>(acc, x1r, x2r, p, cgv[K]), ... );
  if constexpr ((CIDX % SYNCEVERY) == (SYNCEVERY - 1)) __syncthreads();
}

template<int MLO, int FB, int FE, int DELTA, int... C>
__device__ __forceinline__ void run_chunks(ull* __restrict__ acc,
                                           const ull* __restrict__ x1r,
                                           const ull* __restrict__ x2r,
                                           const ull* __restrict__ scg,
                                           std::integer_sequence<int, C...>) {
  ull p = 0;
  ( run_chunk<MLO, FB + C * CHUNK, DELTA, C>(
        acc, x1r, x2r, scg, p,
        std::make_integer_sequence<int,
            ((FE - (FB + C * CHUNK)) < CHUNK ? (FE - (FB + C * CHUNK)) : CHUNK)>{}),
    ... );
}

template<unsigned MASK, int M>
__device__ __forceinline__ void load1(ull* __restrict__ r,
                                      const ull* __restrict__ src, int c) {
  if constexpr ((MASK >> M) & 1u) r[M] = src[M * NCU + c];
}
template<unsigned MASK, int... M>
__device__ __forceinline__ void loadm(ull* __restrict__ r,
                                      const ull* __restrict__ src, int c,
                                      std::integer_sequence<int, M...>) {
  ( load1<MASK, M>(r, src, c), ... );
}

template<int MLO, int... S>
__device__ __forceinline__ void storem(ull* __restrict__ outu,
                                       const ull* __restrict__ acc, int c,
                                       std::integer_sequence<int, S...>) {
  ( (outu[(MLO + S) * NCU + c] = acc[S]), ... );
}

template<int MLO, int MHI, int FB, int FE, int DELTA, unsigned U1, unsigned U2>
__device__ __forceinline__ void rg(const ull* __restrict__ x1u,
                                   const ull* __restrict__ x2u,
                                   ull* __restrict__ outu,
                                   const ull* __restrict__ scg, int c) {
  ull x1r[NM], x2r[NM];
  loadm<U1>(x1r, x1u, c, std::make_integer_sequence<int, NM>{});
  loadm<U2>(x2r, x2u, c, std::make_integer_sequence<int, NM>{});
  ull acc[MHI - MLO] = {};
  run_chunks<MLO, FB, FE, DELTA>(
      acc, x1r, x2r, scg,
      std::make_integer_sequence<int, (FE - FB + CHUNK - 1) / CHUNK>{});
  storem<MLO>(outu, acc, c, std::make_integer_sequence<int, MHI - MLO>{});
}

template<int G>
__device__ __forceinline__ void rung(const ull* __restrict__ x1u,
                                     const ull* __restrict__ x2u,
                                     ull* __restrict__ outu,
                                     const ull* __restrict__ scg, int c) {
  rg<PLAN.mlo[G], PLAN.mhi[G], PLAN.fb[G], PLAN.fb[G + 1], PK.delta[G],
     PLAN.u1[G], PLAN.u2[G]>(x1u, x2u, outu, scg, c);
}

// CTA = (group, b-octet): all 16 warps execute the SAME ~25KB group region
// (one I-stream per SM) on 8 b's x 2 channel-halves, re-converging every
// SYNCEVERY chunks. Grid = 8 x 16 = 128 CTAs -> one uniform wave, 1 CTA/SM.
__global__ void __launch_bounds__(NT, 1)
tp_kernel(const float* __restrict__ x1, const float* __restrict__ x2,
          const float* __restrict__ cg, float* __restrict__ out) {
  __shared__ __align__(16) ull scg[NF2];   // packed cg, f32x2-duplicated
  const int tid = threadIdx.x;
  for (int i = tid; i < NF2; i += NT) {
    ull u = (ull)__float_as_uint(__ldg(cg + d_pidx.v[i]));
    scg[i] = u | (u << 32);
  }
  __syncthreads();

  const int g   = blockIdx.x >> 4;         // group: uniform per CTA
  const int oct = blockIdx.x & 15;         // b-octet
  const int wid = tid >> 5;
  const int b   = oct * 8 + (wid >> 1);    // 8 b per CTA
  const int h   = wid & 1;                 // channel half
  const int c   = h * 32 + (tid & 31);     // f32x2 lane index within row

  const ull* x1u = reinterpret_cast<const ull*>(x1) + b * (NM * NCU);
  const ull* x2u = reinterpret_cast<const ull*>(x2) + b * (NM * NCU);
  ull*       ou  = reinterpret_cast<ull*>(out)      + b * (NM * NCU);

  switch (g) {
    case 0: rung<0>(x1u, x2u, ou, scg, c); break;
    case 1: rung<1>(x1u, x2u, ou, scg, c); break;
    case 2: rung<2>(x1u, x2u, ou, scg, c); break;
    case 3: rung<3>(x1u, x2u, ou, scg, c); break;
    case 4: rung<4>(x1u, x2u, ou, scg, c); break;
    case 5: rung<5>(x1u, x2u, ou, scg, c); break;
    case 6: rung<6>(x1u, x2u, ou, scg, c); break;
    case 7: rung<7>(x1u, x2u, ou, scg, c); break;
  }
}

// ---- generic fallback (only if runtime nnz != compile-time NNZ) ----
__global__ void tp_generic(const float* __restrict__ x1, const float* __restrict__ x2,
                           const float* __restrict__ cg,
                           const int* __restrict__ M1, const int* __restrict__ M2,
                           const int* __restrict__ seg, int nnz,
                           float* __restrict__ out) {
  const int b = blockIdx.x;
  const int c = threadIdx.x;
  const float* x1b = x1 + b * NM * NC;
  const float* x2b = x2 + b * NM * NC;
  float acc = 0.f;
  int cur = seg[0];
  for (int i = 0; i < nnz; ++i) {
    int s = seg[i];
    if (s != cur) { out[(b * NM + cur) * NC + c] = acc; acc = 0.f; cur = s; }
    acc += cg[i] * x1b[M1[i] * NC + c] * x2b[M2[i] * NC + c];
  }
  out[(b * NM + cur) * NC + c] = acc;
}

}  // namespace tp

extern "C" void kernel_launch(void* const* d_in, const int* in_sizes, int n_in,
                              void* d_out, int out_size) {
  const float* x1 = (const float*)d_in[0];
  const float* x2 = (const float*)d_in[1];
  const float* cg = (const float*)d_in[2];
  const int*   M1 = (const int*)  d_in[3];
  const int*   M2 = (const int*)  d_in[4];
  const int*   sg = (const int*)  d_in[5];
  float* out = (float*)d_out;

  if (in_sizes[2] == tp::NNZ) {
    tp::tp_kernel<<<tp::NG * 16, tp::NT>>>(x1, x2, cg, out);
  } else {
    cudaMemsetAsync(d_out, 0, (size_t)out_size * sizeof(float));
    tp::tp_generic<<<tp::NB, tp::NC>>>(x1, x2, cg, M1, M2, sg, in_sizes[2], out);
  }
}